// round 16
// baseline (speedup 1.0000x reference)
#include <cuda_runtime.h>
#include <cuda_fp16.h>
#include <cstdint>
#include <math.h>

#define N_ 128
#define D_ 512
#define L_ 512
#define K_ 512
#define KH 256                   // half spectrum (k-mirror)
#define LH 256                   // half reduction (l-fold)
#define M_ (N_ * D_)

// ---------------- device globals (allocation-free scratch) ----------------
__device__ __half gBc[LH * KH];     // cos basis (l<256, k<256), fp16
__device__ __half gBs[LH * KH];     // sin basis
__device__ float  gCosC[LH];        // cos(c*l), l<256
__device__ float  gA1[D_];          // exp(sigma/511) * a
__device__ float  gA2[D_];          // exp(sigma/511) * (1-a)

// ---------------- helpers ----------------
__device__ __forceinline__ uint32_t smem_u32(const void* p) {
    uint32_t a;
    asm("{ .reg .u64 t; cvta.to.shared.u64 t, %1; cvt.u32.u64 %0, t; }" : "=r"(a) : "l"(p));
    return a;
}
#define CP_ASYNC16(dst, src) asm volatile("cp.async.cg.shared.global [%0], [%1], 16;" :: "r"(dst), "l"(src))
#define CP_COMMIT() asm volatile("cp.async.commit_group;" ::: "memory")

#define LDSM4(R, addr) \
    asm volatile("ldmatrix.sync.aligned.m8n8.x4.shared.b16 {%0,%1,%2,%3}, [%4];" \
        : "=r"((R)[0]), "=r"((R)[1]), "=r"((R)[2]), "=r"((R)[3]) : "r"(addr))
#define LDSM4T(R, addr) \
    asm volatile("ldmatrix.sync.aligned.m8n8.x4.trans.shared.b16 {%0,%1,%2,%3}, [%4];" \
        : "=r"((R)[0]), "=r"((R)[1]), "=r"((R)[2]), "=r"((R)[3]) : "r"(addr))

#define MMA16816(D, A, B0, B1) \
    asm volatile("mma.sync.aligned.m16n8k16.row.col.f32.f16.f16.f32 " \
        "{%0,%1,%2,%3}, {%4,%5,%6,%7}, {%8,%9}, {%0,%1,%2,%3};" \
        : "+f"((D)[0]), "+f"((D)[1]), "+f"((D)[2]), "+f"((D)[3]) \
        : "r"((A)[0]), "r"((A)[1]), "r"((A)[2]), "r"((A)[3]), "r"(B0), "r"(B1))

// ---------------- prep: basis (fp16) + window factors ----------------
__global__ void precompute_kernel(const float* __restrict__ a,
                                  const float* __restrict__ sigma) {
    const int idx = blockIdx.x * blockDim.x + threadIdx.x;
    const float c = (float)(6.283185307179586 / 511.0);
    if (idx < LH * KH) {
        const int l = idx / KH, k = idx - l * KH;
        float s, cc;
        sincosf(c * (float)(l * k), &s, &cc);
        gBc[idx] = __float2half(cc);
        gBs[idx] = __float2half(s);
    }
    if (idx < LH) gCosC[idx] = cosf(c * (float)idx);
    if (idx < D_) {
        const float es = expf(sigma[idx] * (1.0f / 511.0f));
        gA1[idx] = es * a[idx];
        gA2[idx] = es * (1.0f - a[idx]);
    }
}

// ---------------- main: fused fold + dual-GEMM + magnitude ----------------
// CTA 128(M) x 64(N); BK=32, 8 chunks; 8 warps (2Mx4N), warp tile 64x16.
// x loaded LDG->regs one chunk ahead; convert -> double-buffered fp16 u,v tiles;
// one __syncthreads per chunk. B via 2-stage cp.async ring.
#define BK 32
#define NCH (LH / BK)            // 8 chunks
#define AP 80                    // A tile pitch: 32 h = 64B + 16 pad
#define BP 144                   // B pitch: 64 h = 128B + 16 pad
#define AMAT (128 * AP)          // 10240 per A matrix
#define ABUF (2 * AMAT)          // u + v per buffer
#define BMAT (BK * BP)           // 4608 per B matrix
#define BSTG (2 * BMAT)          // 9216 per B stage
#define SM_COSC 0
#define SM_A 1024
#define SM_B (SM_A + 2 * ABUF)                 // 41984
#define SMEM_TOTAL (SM_B + 2 * BSTG)           // 60416 -> 2 CTAs/SM

__device__ __forceinline__ void load_B(uint32_t stg, int col0, int c, int tid) {
    // 2 mats x 32 rows x 8 (16B units) = 512 -> 2 per thread
#pragma unroll
    for (int p = 0; p < 2; ++p) {
        const int u = tid + p * 256;
        const int mat = u >> 8;
        const int r = (u >> 3) & 31;
        const int cu = u & 7;
        const __half* g = mat ? gBs : gBc;
        const __half* src = g + (size_t)(c * BK + r) * KH + col0 + cu * 8;
        CP_ASYNC16(stg + mat * BMAT + r * BP + cu * 16, src);
    }
}

__device__ __forceinline__ void ldg_x(const float* __restrict__ x, int row0,
                                      int cr, int half, int c,
                                      float4* xf, float4* xm) {
    const float* base = x + (size_t)(row0 + cr) * L_;
    const int l0 = c * BK + half * 16;
    const float4* pf = (const float4*)(base + l0);
    const float4* pm = (const float4*)(base + (L_ - 16 - l0));
#pragma unroll
    for (int i = 0; i < 4; ++i) { xf[i] = pf[i]; xm[i] = pm[i]; }
}

__device__ __forceinline__ void convert_store(uint32_t ubase, int cr, int half, int c,
                                              float A1, float A2,
                                              const float* __restrict__ cosc,
                                              const float4* xf, const float4* xm) {
    float f[16], m[16];
#pragma unroll
    for (int i = 0; i < 4; ++i) {
        f[4 * i + 0] = xf[i].x; f[4 * i + 1] = xf[i].y;
        f[4 * i + 2] = xf[i].z; f[4 * i + 3] = xf[i].w;
        // m[j] = x[511 - (l0+j)] ; xm[i] covers descending j
        m[4 * i + 0] = xm[3 - i].w; m[4 * i + 1] = xm[3 - i].z;
        m[4 * i + 2] = xm[3 - i].y; m[4 * i + 3] = xm[3 - i].x;
    }
    const float* cc = cosc + c * BK + half * 16;
    uint32_t up[8], vp[8];
#pragma unroll
    for (int i = 0; i < 8; ++i) {
        const float w0 = __fmaf_rn(-A2, cc[2 * i + 0], A1);
        const float w1 = __fmaf_rn(-A2, cc[2 * i + 1], A1);
        const __half2 uh = __floats2half2_rn(w0 * (f[2 * i] + m[2 * i]),
                                             w1 * (f[2 * i + 1] + m[2 * i + 1]));
        const __half2 vh = __floats2half2_rn(w0 * (f[2 * i] - m[2 * i]),
                                             w1 * (f[2 * i + 1] - m[2 * i + 1]));
        up[i] = *(const uint32_t*)&uh;
        vp[i] = *(const uint32_t*)&vh;
    }
    const uint32_t ua = ubase + cr * AP + half * 32;
    asm volatile("st.shared.v4.b32 [%0], {%1,%2,%3,%4};"
                 :: "r"(ua), "r"(up[0]), "r"(up[1]), "r"(up[2]), "r"(up[3]));
    asm volatile("st.shared.v4.b32 [%0], {%1,%2,%3,%4};"
                 :: "r"(ua + 16), "r"(up[4]), "r"(up[5]), "r"(up[6]), "r"(up[7]));
    asm volatile("st.shared.v4.b32 [%0], {%1,%2,%3,%4};"
                 :: "r"(ua + AMAT), "r"(vp[0]), "r"(vp[1]), "r"(vp[2]), "r"(vp[3]));
    asm volatile("st.shared.v4.b32 [%0], {%1,%2,%3,%4};"
                 :: "r"(ua + AMAT + 16), "r"(vp[4]), "r"(vp[5]), "r"(vp[6]), "r"(vp[7]));
}

__global__ __launch_bounds__(256, 2)
void spectro_fused_kernel(const float* __restrict__ x, float* __restrict__ out) {
    extern __shared__ char smem[];
    const uint32_t sbase = smem_u32(smem);
    const int tid = threadIdx.x;
    const int wid = tid >> 5;
    const int lid = tid & 31;
    const int col0 = blockIdx.x * 64;    // 4 col tiles (k < 256)
    const int row0 = blockIdx.y * 128;   // 512 row tiles
    const int wm = wid >> 2;
    const int wn = wid & 3;

    const int cr   = tid & 127;
    const int half = tid >> 7;
    const int d    = (row0 + cr) & (D_ - 1);
    const float A1 = gA1[d];
    const float A2 = gA2[d];
    const float* cosc = (const float*)(smem + SM_COSC);

    // stage cosC
    if (tid < 64) {
        const float4 v = *(const float4*)(gCosC + tid * 4);
        *(float4*)(smem + SM_COSC + tid * 16) = v;
    }

    float accR[4][2][4];
    float accI[4][2][4];
#pragma unroll
    for (int mt = 0; mt < 4; ++mt)
#pragma unroll
        for (int nt = 0; nt < 2; ++nt)
#pragma unroll
            for (int j = 0; j < 4; ++j) { accR[mt][nt][j] = 0.f; accI[mt][nt][j] = 0.f; }

    const int g8 = lid >> 3;
    const int lr = lid & 7;

    float4 xf[4], xm[4];

    // prologue
    load_B(sbase + SM_B + 0 * BSTG, col0, 0, tid); CP_COMMIT();
    load_B(sbase + SM_B + 1 * BSTG, col0, 1, tid); CP_COMMIT();
    ldg_x(x, row0, cr, half, 0, xf, xm);
    __syncthreads();                                   // cosC visible
    convert_store(sbase + SM_A + 0 * ABUF, cr, half, 0, A1, A2, cosc, xf, xm);
    ldg_x(x, row0, cr, half, 1, xf, xm);
    __syncthreads();                                   // A buf0 visible

    for (int c = 0; c < NCH; ++c) {
        // B(c) resident
        if (c + 1 < NCH) {
            asm volatile("cp.async.wait_group 1;" ::: "memory");
        } else {
            asm volatile("cp.async.wait_group 0;" ::: "memory");
        }

        // ---- MMA on chunk c ----
        const uint32_t ab = sbase + SM_A + (c & 1) * ABUF;
        const uint32_t bb = sbase + SM_B + (c & 1) * BSTG;
#pragma unroll
        for (int kk = 0; kk < 2; ++kk) {
            const int krow = kk * 16 + ((g8 & 1) << 3) + lr;
            const uint32_t bd = bb + krow * BP + wn * 32 + ((g8 >> 1) << 4);
            uint32_t bC[4], bS[4];
            LDSM4T(bC, bd);
            LDSM4T(bS, bd + BMAT);
#pragma unroll
            for (int mt = 0; mt < 4; ++mt) {
                const int row = wm * 64 + mt * 16 + ((g8 & 1) << 3) + lr;
                const uint32_t ad = ab + row * AP + kk * 32 + ((g8 >> 1) << 4);
                uint32_t aU[4], aV[4];
                LDSM4(aU, ad);
                LDSM4(aV, ad + AMAT);
#pragma unroll
                for (int nt = 0; nt < 2; ++nt) {
                    MMA16816(accR[mt][nt], aU, bC[nt * 2], bC[nt * 2 + 1]);
                    MMA16816(accI[mt][nt], aV, bS[nt * 2], bS[nt * 2 + 1]);
                }
            }
        }

        // ---- convert chunk c+1 into the other A buffer; prefetch x(c+2) ----
        if (c + 1 < NCH) {
            convert_store(sbase + SM_A + ((c + 1) & 1) * ABUF, cr, half, c + 1,
                          A1, A2, cosc, xf, xm);
            if (c + 2 < NCH) ldg_x(x, row0, cr, half, c + 2, xf, xm);
        }
        __syncthreads();   // A(c+1) published; MMA(c) done everywhere

        // refill B stage (c&1) with chunk c+2 (stage was read by MMA(c) pre-barrier)
        if (c + 2 < NCH) {
            load_B(sbase + SM_B + (c & 1) * BSTG, col0, c + 2, tid);
            CP_COMMIT();
        }
    }

    // ---- epilogue: magnitude; store column k and its mirror 511-k ----
#pragma unroll
    for (int mt = 0; mt < 4; ++mt) {
#pragma unroll
        for (int nt = 0; nt < 2; ++nt) {
            const int r0 = row0 + wm * 64 + mt * 16 + (lid >> 2);
            const int cc = col0 + wn * 16 + nt * 8 + (lid & 3) * 2;
            float2 o0, o1;
            o0.x = sqrtf(fmaf(accR[mt][nt][0], accR[mt][nt][0],
                              accI[mt][nt][0] * accI[mt][nt][0]));
            o0.y = sqrtf(fmaf(accR[mt][nt][1], accR[mt][nt][1],
                              accI[mt][nt][1] * accI[mt][nt][1]));
            o1.x = sqrtf(fmaf(accR[mt][nt][2], accR[mt][nt][2],
                              accI[mt][nt][2] * accI[mt][nt][2]));
            o1.y = sqrtf(fmaf(accR[mt][nt][3], accR[mt][nt][3],
                              accI[mt][nt][3] * accI[mt][nt][3]));
            float* row_a = out + (size_t)r0 * K_;
            float* row_b = out + (size_t)(r0 + 8) * K_;
            *(float2*)(row_a + cc) = o0;
            *(float2*)(row_b + cc) = o1;
            float2 m0 = {o0.y, o0.x};
            float2 m1 = {o1.y, o1.x};
            *(float2*)(row_a + 510 - cc) = m0;
            *(float2*)(row_b + 510 - cc) = m1;
        }
    }
}

// ---------------------------------------------------------------------------
extern "C" void kernel_launch(void* const* d_in, const int* in_sizes, int n_in,
                              void* d_out, int out_size) {
    const float* x     = (const float*)d_in[0];  // (N, D, L)
    const float* a     = (const float*)d_in[1];  // (D,)
    const float* sigma = (const float*)d_in[2];  // (D,)
    float* out = (float*)d_out;                  // (N, D, K)

    precompute_kernel<<<(LH * KH + 255) / 256, 256>>>(a, sigma);

    static bool attr_set = false;
    if (!attr_set) {
        cudaFuncSetAttribute(spectro_fused_kernel,
                             cudaFuncAttributeMaxDynamicSharedMemorySize, SMEM_TOTAL);
        attr_set = true;
    }
    dim3 grid(KH / 64, M_ / 128);   // (4, 512)
    spectro_fused_kernel<<<grid, 256, SMEM_TOTAL>>>(x, out);
}

// round 17
// speedup vs baseline: 1.7698x; 1.7698x over previous
#include <cuda_runtime.h>
#include <cuda_fp16.h>
#include <cstdint>
#include <math.h>

#define N_ 128
#define D_ 512
#define L_ 512
#define K_ 512
#define KH 256                   // half spectrum (k-mirror)
#define LH 256                   // half reduction (l-fold)
#define M_ (N_ * D_)

// ---------------- device globals (allocation-free scratch) ----------------
__device__ __half gAu[(size_t)M_ * LH];        // 33.5 MB, w*(x[l]+x[511-l])
__device__ __half gAv[(size_t)M_ * LH];        // 33.5 MB, w*(x[l]-x[511-l])
__device__ __half gBc[LH * KH];                // cos basis (l<256, k<256)
__device__ __half gBs[LH * KH];                // sin basis
__device__ float  gCosC[LH];                   // cos(c*l)
__device__ float  gA1[D_];                     // exp(sigma/511) * a
__device__ float  gA2[D_];                     // exp(sigma/511) * (1-a)

// ---------------- helpers ----------------
__device__ __forceinline__ uint32_t smem_u32(const void* p) {
    uint32_t a;
    asm("{ .reg .u64 t; cvta.to.shared.u64 t, %1; cvt.u32.u64 %0, t; }" : "=r"(a) : "l"(p));
    return a;
}
#define CP_ASYNC16(dst, src) asm volatile("cp.async.cg.shared.global [%0], [%1], 16;" :: "r"(dst), "l"(src))
#define CP_COMMIT() asm volatile("cp.async.commit_group;" ::: "memory")

#define LDSM4(R, addr) \
    asm volatile("ldmatrix.sync.aligned.m8n8.x4.shared.b16 {%0,%1,%2,%3}, [%4];" \
        : "=r"((R)[0]), "=r"((R)[1]), "=r"((R)[2]), "=r"((R)[3]) : "r"(addr))
#define LDSM4T(R, addr) \
    asm volatile("ldmatrix.sync.aligned.m8n8.x4.trans.shared.b16 {%0,%1,%2,%3}, [%4];" \
        : "=r"((R)[0]), "=r"((R)[1]), "=r"((R)[2]), "=r"((R)[3]) : "r"(addr))

#define MMA16816(D, A, B0, B1) \
    asm volatile("mma.sync.aligned.m16n8k16.row.col.f32.f16.f16.f32 " \
        "{%0,%1,%2,%3}, {%4,%5,%6,%7}, {%8,%9}, {%0,%1,%2,%3};" \
        : "+f"((D)[0]), "+f"((D)[1]), "+f"((D)[2]), "+f"((D)[3]) \
        : "r"((A)[0]), "r"((A)[1]), "r"((A)[2]), "r"((A)[3]), "r"(B0), "r"(B1))

// ---------------- prep 1: basis (fp16) + cosC + window scalars ----------------
__global__ void precompute_kernel(const float* __restrict__ a,
                                  const float* __restrict__ sigma) {
    const int idx = blockIdx.x * blockDim.x + threadIdx.x;
    const float c = (float)(6.283185307179586 / 511.0);
    if (idx < LH * KH) {
        const int l = idx / KH, k = idx - l * KH;
        float s, cc;
        sincosf(c * (float)(l * k), &s, &cc);
        gBc[idx] = __float2half(cc);
        gBs[idx] = __float2half(s);
    }
    if (idx < LH) gCosC[idx] = cosf(c * (float)idx);
    if (idx < D_) {
        const float es = expf(sigma[idx] * (1.0f / 511.0f));
        gA1[idx] = es * a[idx];
        gA2[idx] = es * (1.0f - a[idx]);
    }
}

// ---------------- prep 2: fold x into u/v fp16 halves (window inline) --------
__global__ __launch_bounds__(256)
void fold_a_kernel(const float* __restrict__ x) {
    const size_t g = (size_t)blockIdx.x * blockDim.x + threadIdx.x; // (m, lq)
    if (g >= (size_t)M_ * (LH / 4)) return;
    const int m  = (int)(g >> 6);          // LH/4 = 64
    const int lq = (int)(g & 63);
    const int d  = m & (D_ - 1);
    const float A1 = gA1[d];
    const float A2 = gA2[d];
    const float4 cc = *(const float4*)(gCosC + lq * 4);
    const float4 xf = *(const float4*)(x + (size_t)m * L_ + lq * 4);
    const float4 xm = *(const float4*)(x + (size_t)m * L_ + 508 - lq * 4);
    const float w[4] = {__fmaf_rn(-A2, cc.x, A1), __fmaf_rn(-A2, cc.y, A1),
                        __fmaf_rn(-A2, cc.z, A1), __fmaf_rn(-A2, cc.w, A1)};
    const float f[4]  = {xf.x, xf.y, xf.z, xf.w};
    const float mr[4] = {xm.w, xm.z, xm.y, xm.x};
    __half u[4], v[4];
#pragma unroll
    for (int i = 0; i < 4; ++i) {
        u[i] = __float2half(w[i] * (f[i] + mr[i]));
        v[i] = __float2half(w[i] * (f[i] - mr[i]));
    }
    ((uint2*)gAu)[g] = *(uint2*)u;
    ((uint2*)gAv)[g] = *(uint2*)v;
}

// ---------------- main: folded dual-GEMM + magnitude ------------------------
// Xr = Au @ C, Xi = Av @ S over K-dim 256; CTA 128(M) x 64(N), BK=64,
// 8 warps as 4M x 2N, warp tile 32x32; 2 CTAs/SM, 2-stage pipeline.
#define BK 64
#define NCH (LH / BK)            // 4 chunks
#define PITCH 144                // 128B data + 16B pad (conflict-free ldmatrix)
#define SA_BYTES (128 * PITCH)   // 18432 per A tile
#define SB_BYTES (64 * PITCH)    // 9216 per B matrix
#define SB_BASE (2 * SA_BYTES)   // Au, Av, then C, S
#define STAGE (SB_BASE + 2 * SB_BYTES)  // 55296
#define SMEM_TOTAL (2 * STAGE)          // 110592 -> 2 CTAs/SM

__device__ __forceinline__ void load_chunk(uint32_t sbuf, int row0, int col0,
                                           int l0, int tid) {
    // Au, Av: 2 x 128 rows x 8 (16B units) = 2048 -> 8 per thread
#pragma unroll
    for (int p = 0; p < 8; ++p) {
        const int u = tid + p * 256;
        const int mat = u >> 10;
        const int r = (u >> 3) & 127;
        const int cu = u & 7;
        const __half* g = mat ? gAv : gAu;
        const __half* src = g + (size_t)(row0 + r) * LH + l0 + cu * 8;
        CP_ASYNC16(sbuf + mat * SA_BYTES + r * PITCH + cu * 16, src);
    }
    // B: 2 matrices x 64 rows x 8 (16B units) = 1024 -> 4 per thread
#pragma unroll
    for (int p = 0; p < 4; ++p) {
        const int u = tid + p * 256;
        const int mat = u >> 9;
        const int r = (u >> 3) & 63;
        const int cu = u & 7;
        const __half* g = mat ? gBs : gBc;
        const __half* src = g + (size_t)(l0 + r) * KH + col0 + cu * 8;
        CP_ASYNC16(sbuf + SB_BASE + mat * SB_BYTES + r * PITCH + cu * 16, src);
    }
}

__global__ __launch_bounds__(256, 2)
void spectro_mma_kernel(float* __restrict__ out) {
    extern __shared__ char smem[];
    const uint32_t sbase = smem_u32(smem);
    const int tid = threadIdx.x;
    const int wid = tid >> 5;
    const int lid = tid & 31;
    const int col0 = blockIdx.x * 64;    // 4 col tiles (k < 256)
    const int row0 = blockIdx.y * 128;   // 512 row tiles
    const int wm = wid & 3;              // 0..3 (M, 32 rows each)
    const int wn = wid >> 2;             // 0..1 (N, 32 cols each)

    float accR[2][4][4];
    float accI[2][4][4];
#pragma unroll
    for (int mt = 0; mt < 2; ++mt)
#pragma unroll
        for (int nt = 0; nt < 4; ++nt)
#pragma unroll
            for (int j = 0; j < 4; ++j) { accR[mt][nt][j] = 0.f; accI[mt][nt][j] = 0.f; }

    const int g8 = lid >> 3;       // 0..3
    const int lr = lid & 7;        // row within 8x8

    load_chunk(sbase, row0, col0, 0, tid);
    CP_COMMIT();

    for (int c = 0; c < NCH; ++c) {
        if (c + 1 < NCH) {
            load_chunk(sbase + ((c + 1) & 1) * STAGE, row0, col0, (c + 1) * BK, tid);
            CP_COMMIT();
            asm volatile("cp.async.wait_group 1;" ::: "memory");
        } else {
            asm volatile("cp.async.wait_group 0;" ::: "memory");
        }
        __syncthreads();

        const uint32_t sa = sbase + (c & 1) * STAGE;
        const uint32_t sb = sa + SB_BASE;
#pragma unroll
        for (int kk = 0; kk < 4; ++kk) {
            // B fragments: 32 cols for this warp (2 LDSM4T per matrix)
            const int krow = kk * 16 + ((g8 & 1) << 3) + lr;
            const uint32_t bd = sb + krow * PITCH + wn * 64 + ((g8 >> 1) << 4);
            uint32_t bC[8], bS[8];
            LDSM4T(bC,     bd);
            LDSM4T(bC + 4, bd + 32);
            LDSM4T(bS,     bd + SB_BYTES);
            LDSM4T(bS + 4, bd + SB_BYTES + 32);
#pragma unroll
            for (int mt = 0; mt < 2; ++mt) {
                const int row = wm * 32 + mt * 16 + ((g8 & 1) << 3) + lr;
                const uint32_t ad = sa + row * PITCH + kk * 32 + ((g8 >> 1) << 4);
                uint32_t aU[4], aV[4];
                LDSM4(aU, ad);
                LDSM4(aV, ad + SA_BYTES);
#pragma unroll
                for (int nt = 0; nt < 4; ++nt) {
                    MMA16816(accR[mt][nt], aU, bC[nt * 2], bC[nt * 2 + 1]);
                    MMA16816(accI[mt][nt], aV, bS[nt * 2], bS[nt * 2 + 1]);
                }
            }
        }
        __syncthreads();
    }

    // ---- epilogue: magnitude; store column k and its mirror 511-k ----
#pragma unroll
    for (int mt = 0; mt < 2; ++mt) {
#pragma unroll
        for (int nt = 0; nt < 4; ++nt) {
            const int r0 = row0 + wm * 32 + mt * 16 + (lid >> 2);
            const int cc = col0 + wn * 32 + nt * 8 + (lid & 3) * 2;
            float2 o0, o1;
            o0.x = sqrtf(fmaf(accR[mt][nt][0], accR[mt][nt][0],
                              accI[mt][nt][0] * accI[mt][nt][0]));
            o0.y = sqrtf(fmaf(accR[mt][nt][1], accR[mt][nt][1],
                              accI[mt][nt][1] * accI[mt][nt][1]));
            o1.x = sqrtf(fmaf(accR[mt][nt][2], accR[mt][nt][2],
                              accI[mt][nt][2] * accI[mt][nt][2]));
            o1.y = sqrtf(fmaf(accR[mt][nt][3], accR[mt][nt][3],
                              accI[mt][nt][3] * accI[mt][nt][3]));
            float* row_a = out + (size_t)r0 * K_;
            float* row_b = out + (size_t)(r0 + 8) * K_;
            *(float2*)(row_a + cc) = o0;
            *(float2*)(row_b + cc) = o1;
            float2 m0 = {o0.y, o0.x};
            float2 m1 = {o1.y, o1.x};
            *(float2*)(row_a + 510 - cc) = m0;
            *(float2*)(row_b + 510 - cc) = m1;
        }
    }
}

// ---------------------------------------------------------------------------
extern "C" void kernel_launch(void* const* d_in, const int* in_sizes, int n_in,
                              void* d_out, int out_size) {
    const float* x     = (const float*)d_in[0];  // (N, D, L)
    const float* a     = (const float*)d_in[1];  // (D,)
    const float* sigma = (const float*)d_in[2];  // (D,)
    float* out = (float*)d_out;                  // (N, D, K)

    precompute_kernel<<<(LH * KH + 255) / 256, 256>>>(a, sigma);
    fold_a_kernel<<<(M_ * (LH / 4) + 255) / 256, 256>>>(x);

    static bool attr_set = false;
    if (!attr_set) {
        cudaFuncSetAttribute(spectro_mma_kernel,
                             cudaFuncAttributeMaxDynamicSharedMemorySize, SMEM_TOTAL);
        attr_set = true;
    }
    dim3 grid(KH / 64, M_ / 128);   // (4, 512)
    spectro_mma_kernel<<<grid, 256, SMEM_TOTAL>>>(out);
}